// round 1
// baseline (speedup 1.0000x reference)
#include <cuda_runtime.h>
#include <cuda_bf16.h>

// Problem constants
#define BSZ   4
#define NSEQ  1024
#define DMODEL 1024
#define NHEAD 16
#define DHEAD 64
#define FFDIM 4096
#define MROWS (BSZ * NSEQ)   // 4096

// ---------------------------------------------------------------------------
// Scratch (device globals; no dynamic allocation allowed)
// ---------------------------------------------------------------------------
__device__ float g_h  [(size_t)MROWS * DMODEL];                 // 16 MB (LN output, reused)
__device__ float g_qkv[(size_t)MROWS * 3 * DMODEL];             // 48 MB
__device__ float g_S  [4ULL * 16 * 1024 * 1024];                // 256 MB scores / probs
__device__ float g_o  [(size_t)MROWS * DMODEL];                 // 16 MB attention out
__device__ float g_ff [(size_t)MROWS * FFDIM];                  // 64 MB

// ---------------------------------------------------------------------------
// LayerNorm: one block per row, 256 threads, D=1024 (4 floats/thread)
// ---------------------------------------------------------------------------
__global__ void __launch_bounds__(256) ln_kernel(
    const float* __restrict__ x, const float* __restrict__ w,
    const float* __restrict__ b, float* __restrict__ out)
{
    int row = blockIdx.x;
    int t = threadIdx.x;
    const float4* xr = (const float4*)(x + (size_t)row * DMODEL);
    float4 v = xr[t];
    float s  = v.x + v.y + v.z + v.w;
    float ss = v.x*v.x + v.y*v.y + v.z*v.z + v.w*v.w;
    #pragma unroll
    for (int o = 16; o; o >>= 1) {
        s  += __shfl_xor_sync(0xffffffffu, s,  o);
        ss += __shfl_xor_sync(0xffffffffu, ss, o);
    }
    __shared__ float rs[8], rss[8];
    int wid = t >> 5, ln = t & 31;
    if (ln == 0) { rs[wid] = s; rss[wid] = ss; }
    __syncthreads();
    if (t < 32) {
        s  = (ln < 8) ? rs[ln]  : 0.f;
        ss = (ln < 8) ? rss[ln] : 0.f;
        #pragma unroll
        for (int o = 4; o; o >>= 1) {
            s  += __shfl_xor_sync(0xffffffffu, s,  o);
            ss += __shfl_xor_sync(0xffffffffu, ss, o);
        }
        if (ln == 0) { rs[0] = s; rss[0] = ss; }
    }
    __syncthreads();
    float mean = rs[0] * (1.0f / DMODEL);
    float var  = rss[0] * (1.0f / DMODEL) - mean * mean;
    float inv  = rsqrtf(var + 1e-5f);
    float4 wv = ((const float4*)w)[t];
    float4 bv = ((const float4*)b)[t];
    float4 o4;
    o4.x = (v.x - mean) * inv * wv.x + bv.x;
    o4.y = (v.y - mean) * inv * wv.y + bv.y;
    o4.z = (v.z - mean) * inv * wv.z + bv.z;
    o4.w = (v.w - mean) * inv * wv.w + bv.w;
    ((float4*)(out + (size_t)row * DMODEL))[t] = o4;
}

// ---------------------------------------------------------------------------
// tanh GELU (matches jax.nn.gelu approximate=True)
// ---------------------------------------------------------------------------
__device__ __forceinline__ float gelu_tanh(float x)
{
    float x3 = x * x * x;
    float u = 0.7978845608028654f * (x + 0.044715f * x3);
    return 0.5f * x * (1.0f + tanhf(u));
}

// ---------------------------------------------------------------------------
// Generic tiled fp32 GEMM: C = epilogue(A @ op(B) + bias)
//   A: [M,K] row-major, lda
//   TRANSB=1: B is W [Nc,K] row-major (C = A @ W^T), ldb = row stride of W
//   TRANSB=0: B is [K,Nc] row-major,                ldb = row stride
//   EPI: 0 = +bias, 1 = *scale, 2 = gelu(+bias), 3 = res + gamma*(+bias)
//   Batched over blockIdx.z = b*Hdim + h with per-b / per-h pointer offsets.
//   Tiles: BM=128, BN=64, BK=16; 256 threads; 8x4 per-thread microtile.
//   All problem dims here are exact multiples (no bounds checks needed).
// ---------------------------------------------------------------------------
template <int TRANSB, int EPI>
__global__ void __launch_bounds__(256) gemm_kernel(
    const float* __restrict__ A, const float* __restrict__ Bm,
    const float* __restrict__ bias, float* __restrict__ C,
    const float* __restrict__ res, const float* __restrict__ gamma,
    int K, int lda, int ldb, int ldc,
    long long sAb, long long sAh, long long sBb, long long sBh,
    long long sCb, long long sCh, int Hdim, float scale)
{
    int bz = blockIdx.z;
    int bb = bz / Hdim, hh = bz % Hdim;
    A  += (size_t)bb * sAb + (size_t)hh * sAh;
    Bm += (size_t)bb * sBb + (size_t)hh * sBh;
    C  += (size_t)bb * sCb + (size_t)hh * sCh;

    int m0 = blockIdx.y * 128;
    int n0 = blockIdx.x * 64;

    __shared__ __align__(16) float As[16][128];
    __shared__ __align__(16) float Bs[16][64];

    int t  = threadIdx.x;
    int ty = t >> 4;          // 0..15  -> rows ty*8 .. ty*8+7
    int tx = t & 15;          // 0..15  -> cols tx*4 .. tx*4+3

    float acc[8][4];
    #pragma unroll
    for (int i = 0; i < 8; i++)
        #pragma unroll
        for (int j = 0; j < 4; j++) acc[i][j] = 0.f;

    int ar = t >> 1, ak = (t & 1) * 8;            // A loads: 128 rows x 8 k
    int br = t >> 2, bk = (t & 3) * 4;            // B loads (TRANSB)
    int bkk = t >> 4, bnn = (t & 15) * 4;         // B loads (!TRANSB)

    const float* Arow = A + (size_t)(m0 + ar) * lda + ak;
    const float* Brow;
    if (TRANSB) Brow = Bm + (size_t)(n0 + br) * ldb + bk;
    else        Brow = Bm + (size_t)bkk * ldb + n0 + bnn;

    for (int k0 = 0; k0 < K; k0 += 16) {
        float4 a0 = *(const float4*)(Arow + k0);
        float4 a1 = *(const float4*)(Arow + k0 + 4);
        As[ak + 0][ar] = a0.x; As[ak + 1][ar] = a0.y;
        As[ak + 2][ar] = a0.z; As[ak + 3][ar] = a0.w;
        As[ak + 4][ar] = a1.x; As[ak + 5][ar] = a1.y;
        As[ak + 6][ar] = a1.z; As[ak + 7][ar] = a1.w;
        if (TRANSB) {
            float4 bv = *(const float4*)(Brow + k0);
            Bs[bk + 0][br] = bv.x; Bs[bk + 1][br] = bv.y;
            Bs[bk + 2][br] = bv.z; Bs[bk + 3][br] = bv.w;
        } else {
            float4 bv = *(const float4*)(Brow + (size_t)k0 * ldb);
            *(float4*)&Bs[bkk][bnn] = bv;
        }
        __syncthreads();
        #pragma unroll
        for (int kk = 0; kk < 16; kk++) {
            float4 a0v = *(const float4*)&As[kk][ty * 8];
            float4 a1v = *(const float4*)&As[kk][ty * 8 + 4];
            float4 bvv = *(const float4*)&Bs[kk][tx * 4];
            float av[8] = {a0v.x, a0v.y, a0v.z, a0v.w, a1v.x, a1v.y, a1v.z, a1v.w};
            float bv[4] = {bvv.x, bvv.y, bvv.z, bvv.w};
            #pragma unroll
            for (int i = 0; i < 8; i++)
                #pragma unroll
                for (int j = 0; j < 4; j++)
                    acc[i][j] += av[i] * bv[j];
        }
        __syncthreads();
    }

    // Epilogue
    float4 bias4 = make_float4(0.f, 0.f, 0.f, 0.f);
    if ((EPI == 0 || EPI == 2 || EPI == 3) && bias)
        bias4 = *(const float4*)(bias + n0 + tx * 4);
    float4 g4 = make_float4(0.f, 0.f, 0.f, 0.f);
    if (EPI == 3) g4 = *(const float4*)(gamma + n0 + tx * 4);

    #pragma unroll
    for (int i = 0; i < 8; i++) {
        int row = m0 + ty * 8 + i;
        float4 v;
        v.x = acc[i][0] + bias4.x;
        v.y = acc[i][1] + bias4.y;
        v.z = acc[i][2] + bias4.z;
        v.w = acc[i][3] + bias4.w;
        if (EPI == 1) { v.x *= scale; v.y *= scale; v.z *= scale; v.w *= scale; }
        if (EPI == 2) {
            v.x = gelu_tanh(v.x); v.y = gelu_tanh(v.y);
            v.z = gelu_tanh(v.z); v.w = gelu_tanh(v.w);
        }
        if (EPI == 3) {
            float4 r4 = *(const float4*)(res + (size_t)row * ldc + n0 + tx * 4);
            v.x = r4.x + g4.x * v.x;
            v.y = r4.y + g4.y * v.y;
            v.z = r4.z + g4.z * v.z;
            v.w = r4.w + g4.w * v.w;
        }
        *(float4*)(C + (size_t)row * ldc + n0 + tx * 4) = v;
    }
}

// ---------------------------------------------------------------------------
// Fused talking-heads: pre-softmax head mix -> softmax -> post-softmax head mix
// One block per (b, i). Reads S[b,:,i,:] (16x1024) once, writes back in place.
// Dynamic smem: 2 * 16 * 1024 * 4 = 128 KB.
// ---------------------------------------------------------------------------
__global__ void __launch_bounds__(256) attn_mix_softmax(
    const float* __restrict__ wl, const float* __restrict__ bl,
    const float* __restrict__ ww, const float* __restrict__ bw,
    float* __restrict__ S)
{
    extern __shared__ float sm[];
    float* Ssh = sm;                    // [16][1024]
    float* Psh = sm + NHEAD * NSEQ;     // [16][1024]
    __shared__ float wls[256], wws[256], bls[16], bws[16];

    int t = threadIdx.x;
    int b = blockIdx.x >> 10;
    int i = blockIdx.x & 1023;

    wls[t] = wl[t];
    wws[t] = ww[t];
    if (t < 16) { bls[t] = bl[t]; bws[t] = bw[t]; }

    float* Sg = S + (size_t)(b * NHEAD) * NSEQ * NSEQ + (size_t)i * NSEQ;

    #pragma unroll
    for (int h = 0; h < NHEAD; h++)
        ((float4*)(Ssh + h * NSEQ))[t] = ((const float4*)(Sg + (size_t)h * NSEQ * NSEQ))[t];
    __syncthreads();

    // Pre-softmax mixing: Psh[g][j] = bl[g] + sum_h wl[g,h] * Ssh[h][j]
    #pragma unroll
    for (int jj = 0; jj < 4; jj++) {
        int j = t + jj * 256;
        float sv[16];
        #pragma unroll
        for (int h = 0; h < 16; h++) sv[h] = Ssh[h * NSEQ + j];
        #pragma unroll
        for (int g = 0; g < 16; g++) {
            float acc = bls[g];
            #pragma unroll
            for (int h = 0; h < 16; h++) acc += wls[g * 16 + h] * sv[h];
            Psh[g * NSEQ + j] = acc;
        }
    }
    __syncthreads();

    // Softmax over j for each of the 16 rows; warp w handles rows w, w+8
    int w = t >> 5, l = t & 31;
    for (int g = w; g < 16; g += 8) {
        float* row = Psh + g * NSEQ;
        float mx = -1e30f;
        for (int m = l; m < NSEQ; m += 32) mx = fmaxf(mx, row[m]);
        #pragma unroll
        for (int o = 16; o; o >>= 1) mx = fmaxf(mx, __shfl_xor_sync(0xffffffffu, mx, o));
        float sum = 0.f;
        for (int m = l; m < NSEQ; m += 32) {
            float e = __expf(row[m] - mx);
            row[m] = e;
            sum += e;
        }
        #pragma unroll
        for (int o = 16; o; o >>= 1) sum += __shfl_xor_sync(0xffffffffu, sum, o);
        float inv = 1.f / sum;
        for (int m = l; m < NSEQ; m += 32) row[m] *= inv;
    }
    __syncthreads();

    // Post-softmax mixing: Ssh[g][j] = bw[g] + sum_h ww[g,h] * Psh[h][j]
    #pragma unroll
    for (int jj = 0; jj < 4; jj++) {
        int j = t + jj * 256;
        float pv[16];
        #pragma unroll
        for (int h = 0; h < 16; h++) pv[h] = Psh[h * NSEQ + j];
        #pragma unroll
        for (int g = 0; g < 16; g++) {
            float acc = bws[g];
            #pragma unroll
            for (int h = 0; h < 16; h++) acc += wws[g * 16 + h] * pv[h];
            Ssh[g * NSEQ + j] = acc;
        }
    }
    __syncthreads();

    #pragma unroll
    for (int h = 0; h < NHEAD; h++)
        ((float4*)(Sg + (size_t)h * NSEQ * NSEQ))[t] = ((const float4*)(Ssh + h * NSEQ))[t];
}

// ---------------------------------------------------------------------------
// Launch
// ---------------------------------------------------------------------------
extern "C" void kernel_launch(void* const* d_in, const int* in_sizes, int n_in,
                              void* d_out, int out_size)
{
    const float* x      = (const float*)d_in[0];
    const float* ln1_w  = (const float*)d_in[1];
    const float* ln1_b  = (const float*)d_in[2];
    const float* qkv_w  = (const float*)d_in[3];
    const float* qkv_b  = (const float*)d_in[4];
    const float* pl_w   = (const float*)d_in[5];
    const float* pl_b   = (const float*)d_in[6];
    const float* pw_w   = (const float*)d_in[7];
    const float* pw_b   = (const float*)d_in[8];
    const float* out_w  = (const float*)d_in[9];
    const float* out_b  = (const float*)d_in[10];
    const float* gamma1 = (const float*)d_in[11];
    const float* ln2_w  = (const float*)d_in[12];
    const float* ln2_b  = (const float*)d_in[13];
    const float* fc1_w  = (const float*)d_in[14];
    const float* fc1_b  = (const float*)d_in[15];
    const float* fc2_w  = (const float*)d_in[16];
    const float* fc2_b  = (const float*)d_in[17];
    const float* gamma2 = (const float*)d_in[18];
    float* out = (float*)d_out;

    float *hbuf, *qkv, *S, *obuf, *ff;
    cudaGetSymbolAddress((void**)&hbuf, g_h);
    cudaGetSymbolAddress((void**)&qkv,  g_qkv);
    cudaGetSymbolAddress((void**)&S,    g_S);
    cudaGetSymbolAddress((void**)&obuf, g_o);
    cudaGetSymbolAddress((void**)&ff,   g_ff);

    cudaFuncSetAttribute(attn_mix_softmax,
                         cudaFuncAttributeMaxDynamicSharedMemorySize, 131072);

    const long long NN  = (long long)NSEQ * NSEQ;        // 1,048,576
    const long long SQK = (long long)NSEQ * 3 * DMODEL;  // per-batch qkv stride

    // 1) LN1: x -> hbuf
    ln_kernel<<<MROWS, 256>>>(x, ln1_w, ln1_b, hbuf);

    // 2) qkv = hbuf @ qkv_w^T + qkv_b   [4096,1024]x[3072,1024]^T
    gemm_kernel<1, 0><<<dim3(3 * DMODEL / 64, MROWS / 128, 1), 256>>>(
        hbuf, qkv_w, qkv_b, qkv, nullptr, nullptr,
        DMODEL, DMODEL, DMODEL, 3 * DMODEL,
        0, 0, 0, 0, 0, 0, 1, 1.f);

    // 3) S[b,h] = (Q K^T) / 8      batched over 64 (b,h) pairs, K=64
    gemm_kernel<1, 1><<<dim3(NSEQ / 64, NSEQ / 128, BSZ * NHEAD), 256>>>(
        qkv, qkv + DMODEL, nullptr, S, nullptr, nullptr,
        DHEAD, 3 * DMODEL, 3 * DMODEL, NSEQ,
        SQK, DHEAD, SQK, DHEAD, (long long)NHEAD * NN, NN, NHEAD, 0.125f);

    // 4) talking-heads mix -> softmax -> mix (in place on S)
    attn_mix_softmax<<<BSZ * NSEQ, 256, 131072>>>(pl_w, pl_b, pw_w, pw_b, S);

    // 5) O[b,h] = P2 @ V   -> obuf in [B,N,H*DH] layout
    gemm_kernel<0, 0><<<dim3(DHEAD / 64, NSEQ / 128, BSZ * NHEAD), 256>>>(
        S, qkv + 2 * DMODEL, nullptr, obuf, nullptr, nullptr,
        NSEQ, NSEQ, 3 * DMODEL, DMODEL,
        (long long)NHEAD * NN, NN, SQK, DHEAD,
        (long long)NSEQ * DMODEL, DHEAD, NHEAD, 1.f);

    // 6) x1 = x + gamma1 * (obuf @ out_w^T + out_b)   -> d_out
    gemm_kernel<1, 3><<<dim3(DMODEL / 64, MROWS / 128, 1), 256>>>(
        obuf, out_w, out_b, out, x, gamma1,
        DMODEL, DMODEL, DMODEL, DMODEL,
        0, 0, 0, 0, 0, 0, 1, 1.f);

    // 7) LN2: d_out -> hbuf
    ln_kernel<<<MROWS, 256>>>(out, ln2_w, ln2_b, hbuf);

    // 8) ff = gelu(hbuf @ fc1_w^T + fc1_b)
    gemm_kernel<1, 2><<<dim3(FFDIM / 64, MROWS / 128, 1), 256>>>(
        hbuf, fc1_w, fc1_b, ff, nullptr, nullptr,
        DMODEL, DMODEL, DMODEL, FFDIM,
        0, 0, 0, 0, 0, 0, 1, 1.f);

    // 9) out = x1 + gamma2 * (ff @ fc2_w^T + fc2_b)   (in place on d_out)
    gemm_kernel<1, 3><<<dim3(DMODEL / 64, MROWS / 128, 1), 256>>>(
        ff, fc2_w, fc2_b, out, out, gamma2,
        FFDIM, FFDIM, FFDIM, DMODEL,
        0, 0, 0, 0, 0, 0, 1, 1.f);
}

// round 2
// speedup vs baseline: 3.0412x; 3.0412x over previous
#include <cuda_runtime.h>
#include <cstdint>

// Problem constants
#define BSZ    4
#define NSEQ   1024
#define DMODEL 1024
#define NHEAD  16
#define DHEAD  64
#define FFDIM  4096
#define MROWS  (BSZ * NSEQ)   // 4096

// ---------------------------------------------------------------------------
// Scratch (device globals; no dynamic allocation allowed)
// ---------------------------------------------------------------------------
__device__ float g_h  [(size_t)MROWS * DMODEL];
__device__ float g_qkv[(size_t)MROWS * 3 * DMODEL];
__device__ float g_S  [4ULL * 16 * 1024 * 1024];        // 256 MB scores/probs
__device__ float g_o  [(size_t)MROWS * DMODEL];
__device__ float g_ff [(size_t)MROWS * FFDIM];
__device__ float g_wq [3 * DMODEL * DMODEL];            // tf32-rounded weights
__device__ float g_wo [DMODEL * DMODEL];
__device__ float g_wf1[(size_t)FFDIM * DMODEL];
__device__ float g_wf2[(size_t)FFDIM * DMODEL];

// ---------------------------------------------------------------------------
// Helpers
// ---------------------------------------------------------------------------
__device__ __forceinline__ float tf32r(float x) {
    unsigned u;
    asm("cvt.rna.tf32.f32 %0, %1;" : "=r"(u) : "f"(x));
    return __uint_as_float(u);
}

__device__ __forceinline__ void cpa16(float* s, const float* g) {
    unsigned sa = (unsigned)__cvta_generic_to_shared(s);
    asm volatile("cp.async.cg.shared.global [%0], [%1], 16;" :: "r"(sa), "l"(g));
}

__device__ __forceinline__ void mma8(float* c, const unsigned* a, const unsigned* b) {
    asm volatile(
        "mma.sync.aligned.m16n8k8.row.col.f32.tf32.tf32.f32 "
        "{%0,%1,%2,%3}, {%4,%5,%6,%7}, {%8,%9}, {%0,%1,%2,%3};"
        : "+f"(c[0]), "+f"(c[1]), "+f"(c[2]), "+f"(c[3])
        : "r"(a[0]), "r"(a[1]), "r"(a[2]), "r"(a[3]), "r"(b[0]), "r"(b[1]));
}

__device__ __forceinline__ float gelu_tanh(float x) {
    float x3 = x * x * x;
    float u = 0.7978845608028654f * (x + 0.044715f * x3);
    return 0.5f * x * (1.0f + tanhf(u));
}

// ---------------------------------------------------------------------------
// Weight prep: round to tf32 (rna) so HMMA truncation is exact afterwards
// ---------------------------------------------------------------------------
__global__ void round_k(const float* __restrict__ src, float* __restrict__ dst, int n4)
{
    int i = blockIdx.x * blockDim.x + threadIdx.x;
    if (i < n4) {
        float4 v = ((const float4*)src)[i];
        v.x = tf32r(v.x); v.y = tf32r(v.y); v.z = tf32r(v.z); v.w = tf32r(v.w);
        ((float4*)dst)[i] = v;
    }
}

// ---------------------------------------------------------------------------
// LayerNorm (output feeds a GEMM A operand -> always tf32-round the result)
// ---------------------------------------------------------------------------
__global__ void __launch_bounds__(256) ln_kernel(
    const float* __restrict__ x, const float* __restrict__ w,
    const float* __restrict__ b, float* __restrict__ out)
{
    int row = blockIdx.x;
    int t = threadIdx.x;
    const float4* xr = (const float4*)(x + (size_t)row * DMODEL);
    float4 v = xr[t];
    float s  = v.x + v.y + v.z + v.w;
    float ss = v.x*v.x + v.y*v.y + v.z*v.z + v.w*v.w;
    #pragma unroll
    for (int o = 16; o; o >>= 1) {
        s  += __shfl_xor_sync(0xffffffffu, s,  o);
        ss += __shfl_xor_sync(0xffffffffu, ss, o);
    }
    __shared__ float rs[8], rss[8];
    int wid = t >> 5, ln = t & 31;
    if (ln == 0) { rs[wid] = s; rss[wid] = ss; }
    __syncthreads();
    if (t < 32) {
        s  = (ln < 8) ? rs[ln]  : 0.f;
        ss = (ln < 8) ? rss[ln] : 0.f;
        #pragma unroll
        for (int o = 4; o; o >>= 1) {
            s  += __shfl_xor_sync(0xffffffffu, s,  o);
            ss += __shfl_xor_sync(0xffffffffu, ss, o);
        }
        if (ln == 0) { rs[0] = s; rss[0] = ss; }
    }
    __syncthreads();
    float mean = rs[0] * (1.0f / DMODEL);
    float var  = rss[0] * (1.0f / DMODEL) - mean * mean;
    float inv  = rsqrtf(var + 1e-5f);
    float4 wv = ((const float4*)w)[t];
    float4 bv = ((const float4*)b)[t];
    float4 o4;
    o4.x = tf32r((v.x - mean) * inv * wv.x + bv.x);
    o4.y = tf32r((v.y - mean) * inv * wv.y + bv.y);
    o4.z = tf32r((v.z - mean) * inv * wv.z + bv.z);
    o4.w = tf32r((v.w - mean) * inv * wv.w + bv.w);
    ((float4*)(out + (size_t)row * DMODEL))[t] = o4;
}

// ---------------------------------------------------------------------------
// TF32 tensor-core GEMM.
//   Block tile BM=128 x BN x BK=32, 256 threads (8 warps), warp tile 32 x BN/2.
//   mma.sync m16n8k8 tf32, cp.async double-buffered smem.
//   TRANSB=1: B is [N,K] row-major (C = A @ B^T), smem Bs[n][k] stride 36
//   TRANSB=0: B is [K,N] row-major,               smem Bs[k][n] stride BN+8
//   As is [m][k] stride 36 (conflict-free for both copy and fragment loads).
//   EPI: 0=+bias(opt)  1=*scale  2=gelu(+bias)  3=res+gamma*(+bias)
//   ROUND: tf32-round C (when C feeds another GEMM as an A operand)
// ---------------------------------------------------------------------------
template <int BN, int TRANSB, int EPI, int ROUND>
__global__ void __launch_bounds__(256, 2) gemm_tc(
    const float* __restrict__ A, const float* __restrict__ Bm,
    const float* __restrict__ bias, float* __restrict__ C,
    const float* __restrict__ res, const float* __restrict__ gamma,
    int K, int lda, int ldb, int ldc,
    long long sAb, long long sAh, long long sBb, long long sBh,
    long long sCb, long long sCh, int Hdim, float scale)
{
    constexpr int BM = 128, BK = 32;
    constexpr int SA  = 36;                 // As [m][k] row stride
    constexpr int SBT = 36;                 // Bs [n][k] row stride (TRANSB=1)
    constexpr int SBN = BN + 8;             // Bs [k][n] row stride (TRANSB=0)
    constexpr int ASTG = BM * SA;
    constexpr int BSTG = TRANSB ? BN * SBT : BK * SBN;
    constexpr int WN = BN / 2;
    constexpr int MI = 2, NI = WN / 8;

    extern __shared__ float smem_g[];
    float* As = smem_g;
    float* Bs = smem_g + 2 * ASTG;

    int bz = blockIdx.z;
    int bb = bz / Hdim, hh = bz - bb * Hdim;
    A  += (size_t)bb * sAb + (size_t)hh * sAh;
    Bm += (size_t)bb * sBb + (size_t)hh * sBh;
    C  += (size_t)bb * sCb + (size_t)hh * sCh;

    int m0 = blockIdx.y * BM;
    int n0 = blockIdx.x * BN;

    int t = threadIdx.x;
    int lane = t & 31, wid = t >> 5;
    int g = lane >> 2, q4 = lane & 3;
    int wm0 = (wid & 3) * 32;
    int wn0 = (wid >> 2) * WN;

    float acc[MI][NI][4];
    #pragma unroll
    for (int mi = 0; mi < MI; mi++)
        #pragma unroll
        for (int ni = 0; ni < NI; ni++)
            #pragma unroll
            for (int r = 0; r < 4; r++) acc[mi][ni][r] = 0.f;

    const float* Abase = A + (size_t)m0 * lda;
    const float* Bbase = TRANSB ? (Bm + (size_t)n0 * ldb) : (Bm + n0);

    int KT = K / BK;

    auto issue = [&](int stage, int kt) {
        float* Ad = As + stage * ASTG;
        const float* Asrc = Abase + kt * BK;
        #pragma unroll
        for (int i2 = 0; i2 < 4; i2++) {
            int c = i2 * 256 + t;
            int row = c >> 3, ch = (c & 7) << 2;
            cpa16(Ad + row * SA + ch, Asrc + (size_t)row * lda + ch);
        }
        float* Bd = Bs + stage * BSTG;
        if (TRANSB) {
            const float* Bsrc = Bbase + kt * BK;
            #pragma unroll
            for (int i2 = 0; i2 < BN / 32; i2++) {
                int c = i2 * 256 + t;
                int row = c >> 3, ch = (c & 7) << 2;
                cpa16(Bd + row * SBT + ch, Bsrc + (size_t)row * ldb + ch);
            }
        } else {
            const float* Bsrc = Bbase + (size_t)kt * BK * ldb;
            #pragma unroll
            for (int i2 = 0; i2 < (BK * BN) / 1024; i2++) {   // BN=64 -> 2
                int c = i2 * 256 + t;
                int row = c >> 4, ch = (c & 15) << 2;
                cpa16(Bd + row * SBN + ch, Bsrc + (size_t)row * ldb + ch);
            }
        }
    };

    auto compute = [&](int stage) {
        const float* Asg = As + stage * ASTG;
        const float* Bsg = Bs + stage * BSTG;
        #pragma unroll
        for (int ks = 0; ks < 4; ks++) {
            unsigned a[MI][4];
            #pragma unroll
            for (int mi = 0; mi < MI; mi++) {
                const float* p = Asg + (wm0 + mi * 16 + g) * SA + ks * 8 + q4;
                a[mi][0] = __float_as_uint(p[0]);
                a[mi][1] = __float_as_uint(p[8 * SA]);
                a[mi][2] = __float_as_uint(p[4]);
                a[mi][3] = __float_as_uint(p[8 * SA + 4]);
            }
            unsigned b[NI][2];
            #pragma unroll
            for (int ni = 0; ni < NI; ni++) {
                if (TRANSB) {
                    const float* p = Bsg + (wn0 + ni * 8 + g) * SBT + ks * 8 + q4;
                    b[ni][0] = __float_as_uint(p[0]);
                    b[ni][1] = __float_as_uint(p[4]);
                } else {
                    const float* p = Bsg + (ks * 8 + q4) * SBN + wn0 + ni * 8 + g;
                    b[ni][0] = __float_as_uint(p[0]);
                    b[ni][1] = __float_as_uint(p[4 * SBN]);
                }
            }
            #pragma unroll
            for (int mi = 0; mi < MI; mi++)
                #pragma unroll
                for (int ni = 0; ni < NI; ni++)
                    mma8(acc[mi][ni], a[mi], b[ni]);
        }
    };

    issue(0, 0);
    asm volatile("cp.async.commit_group;");
    for (int kt = 0; kt < KT; kt++) {
        if (kt + 1 < KT) {
            issue((kt + 1) & 1, kt + 1);
            asm volatile("cp.async.commit_group;");
            asm volatile("cp.async.wait_group 1;");
        } else {
            asm volatile("cp.async.wait_group 0;");
        }
        __syncthreads();
        compute(kt & 1);
        __syncthreads();
    }

    // Epilogue
    #pragma unroll
    for (int mi = 0; mi < MI; mi++) {
        int r0 = m0 + wm0 + mi * 16 + g;
        #pragma unroll
        for (int ni = 0; ni < NI; ni++) {
            int cb = n0 + wn0 + ni * 8 + 2 * q4;
            float bx = 0.f, by = 0.f;
            if ((EPI == 0 || EPI == 2 || EPI == 3) && bias) {
                float2 b2 = *(const float2*)(bias + cb);
                bx = b2.x; by = b2.y;
            }
            float* a4 = acc[mi][ni];
            float v0 = a4[0] + bx, v1 = a4[1] + by;
            float v2 = a4[2] + bx, v3 = a4[3] + by;
            if (EPI == 1) { v0 *= scale; v1 *= scale; v2 *= scale; v3 *= scale; }
            if (EPI == 2) {
                v0 = gelu_tanh(v0); v1 = gelu_tanh(v1);
                v2 = gelu_tanh(v2); v3 = gelu_tanh(v3);
            }
            if (EPI == 3) {
                float2 g2 = *(const float2*)(gamma + cb);
                float2 rA = *(const float2*)(res + (size_t)r0 * ldc + cb);
                float2 rB = *(const float2*)(res + (size_t)(r0 + 8) * ldc + cb);
                v0 = rA.x + g2.x * v0; v1 = rA.y + g2.y * v1;
                v2 = rB.x + g2.x * v2; v3 = rB.y + g2.y * v3;
            }
            if (ROUND) {
                v0 = tf32r(v0); v1 = tf32r(v1); v2 = tf32r(v2); v3 = tf32r(v3);
            }
            *(float2*)(C + (size_t)r0 * ldc + cb)       = make_float2(v0, v1);
            *(float2*)(C + (size_t)(r0 + 8) * ldc + cb) = make_float2(v2, v3);
        }
    }
}

// ---------------------------------------------------------------------------
// Fused talking-heads: mix -> softmax -> mix, in place on S. 512 threads.
// Output tf32-rounded (feeds P@V tensor GEMM).
// ---------------------------------------------------------------------------
__global__ void __launch_bounds__(512) attn_mix_softmax(
    const float* __restrict__ wl, const float* __restrict__ bl,
    const float* __restrict__ ww, const float* __restrict__ bw,
    float* __restrict__ S)
{
    extern __shared__ float sm[];
    float* Ssh = sm;                    // [16][1024]
    float* Psh = sm + NHEAD * NSEQ;     // [16][1024]
    __shared__ float wls[256], wws[256], bls[16], bws[16];

    int t = threadIdx.x;
    int b = blockIdx.x >> 10;
    int i = blockIdx.x & 1023;

    if (t < 256) { wls[t] = wl[t]; wws[t] = ww[t]; }
    if (t < 16)  { bls[t] = bl[t]; bws[t] = bw[t]; }

    float* Sg = S + (size_t)(b * NHEAD) * NSEQ * NSEQ + (size_t)i * NSEQ;

    #pragma unroll
    for (int ii = 0; ii < 8; ii++) {
        int idx4 = ii * 512 + t;
        int h = idx4 >> 8, j4 = idx4 & 255;
        ((float4*)(Ssh + h * NSEQ))[j4] =
            ((const float4*)(Sg + (size_t)h * NSEQ * NSEQ))[j4];
    }
    __syncthreads();

    // Pre-softmax mixing
    #pragma unroll
    for (int jj = 0; jj < 2; jj++) {
        int j = t + jj * 512;
        float sv[16];
        #pragma unroll
        for (int h = 0; h < 16; h++) sv[h] = Ssh[h * NSEQ + j];
        #pragma unroll
        for (int gg = 0; gg < 16; gg++) {
            float acc = bls[gg];
            #pragma unroll
            for (int h = 0; h < 16; h++) acc += wls[gg * 16 + h] * sv[h];
            Psh[gg * NSEQ + j] = acc;
        }
    }
    __syncthreads();

    // Softmax: one warp per head-row
    {
        int w = t >> 5, l = t & 31;
        float* row = Psh + w * NSEQ;
        float mx = -1e30f;
        for (int m = l; m < NSEQ; m += 32) mx = fmaxf(mx, row[m]);
        #pragma unroll
        for (int o = 16; o; o >>= 1) mx = fmaxf(mx, __shfl_xor_sync(0xffffffffu, mx, o));
        float sum = 0.f;
        for (int m = l; m < NSEQ; m += 32) {
            float e = __expf(row[m] - mx);
            row[m] = e;
            sum += e;
        }
        #pragma unroll
        for (int o = 16; o; o >>= 1) sum += __shfl_xor_sync(0xffffffffu, sum, o);
        float inv = 1.f / sum;
        for (int m = l; m < NSEQ; m += 32) row[m] *= inv;
    }
    __syncthreads();

    // Post-softmax mixing (+ tf32 rounding for the P@V GEMM)
    #pragma unroll
    for (int jj = 0; jj < 2; jj++) {
        int j = t + jj * 512;
        float pv[16];
        #pragma unroll
        for (int h = 0; h < 16; h++) pv[h] = Psh[h * NSEQ + j];
        #pragma unroll
        for (int gg = 0; gg < 16; gg++) {
            float acc = bws[gg];
            #pragma unroll
            for (int h = 0; h < 16; h++) acc += wws[gg * 16 + h] * pv[h];
            Ssh[gg * NSEQ + j] = tf32r(acc);
        }
    }
    __syncthreads();

    #pragma unroll
    for (int ii = 0; ii < 8; ii++) {
        int idx4 = ii * 512 + t;
        int h = idx4 >> 8, j4 = idx4 & 255;
        ((float4*)(Sg + (size_t)h * NSEQ * NSEQ))[j4] =
            ((const float4*)(Ssh + h * NSEQ))[j4];
    }
}

// ---------------------------------------------------------------------------
// Launch
// ---------------------------------------------------------------------------
extern "C" void kernel_launch(void* const* d_in, const int* in_sizes, int n_in,
                              void* d_out, int out_size)
{
    const float* x      = (const float*)d_in[0];
    const float* ln1_w  = (const float*)d_in[1];
    const float* ln1_b  = (const float*)d_in[2];
    const float* qkv_w  = (const float*)d_in[3];
    const float* qkv_b  = (const float*)d_in[4];
    const float* pl_w   = (const float*)d_in[5];
    const float* pl_b   = (const float*)d_in[6];
    const float* pw_w   = (const float*)d_in[7];
    const float* pw_b   = (const float*)d_in[8];
    const float* out_w  = (const float*)d_in[9];
    const float* out_b  = (const float*)d_in[10];
    const float* gamma1 = (const float*)d_in[11];
    const float* ln2_w  = (const float*)d_in[12];
    const float* ln2_b  = (const float*)d_in[13];
    const float* fc1_w  = (const float*)d_in[14];
    const float* fc1_b  = (const float*)d_in[15];
    const float* fc2_w  = (const float*)d_in[16];
    const float* fc2_b  = (const float*)d_in[17];
    const float* gamma2 = (const float*)d_in[18];
    float* out = (float*)d_out;

    float *hbuf, *qkvp, *S, *obuf, *ff, *wq, *wo, *wf1, *wf2;
    cudaGetSymbolAddress((void**)&hbuf, g_h);
    cudaGetSymbolAddress((void**)&qkvp, g_qkv);
    cudaGetSymbolAddress((void**)&S,    g_S);
    cudaGetSymbolAddress((void**)&obuf, g_o);
    cudaGetSymbolAddress((void**)&ff,   g_ff);
    cudaGetSymbolAddress((void**)&wq,   g_wq);
    cudaGetSymbolAddress((void**)&wo,   g_wo);
    cudaGetSymbolAddress((void**)&wf1,  g_wf1);
    cudaGetSymbolAddress((void**)&wf2,  g_wf2);

    cudaFuncSetAttribute(attn_mix_softmax,
                         cudaFuncAttributeMaxDynamicSharedMemorySize, 131072);
    cudaFuncSetAttribute(gemm_tc<128,1,0,1>, cudaFuncAttributeMaxDynamicSharedMemorySize, 73728);
    cudaFuncSetAttribute(gemm_tc<128,1,1,0>, cudaFuncAttributeMaxDynamicSharedMemorySize, 73728);
    cudaFuncSetAttribute(gemm_tc<128,1,2,1>, cudaFuncAttributeMaxDynamicSharedMemorySize, 73728);
    cudaFuncSetAttribute(gemm_tc<128,1,3,0>, cudaFuncAttributeMaxDynamicSharedMemorySize, 73728);
    cudaFuncSetAttribute(gemm_tc<64,0,0,1>,  cudaFuncAttributeMaxDynamicSharedMemorySize, 55296);

    const long long NN  = (long long)NSEQ * NSEQ;
    const long long SQK = (long long)NSEQ * 3 * DMODEL;

    // 0) Round weights to tf32 once per launch
    round_k<<<3072, 256>>>(qkv_w, wq,  3 * DMODEL * DMODEL / 4);
    round_k<<<1024, 256>>>(out_w, wo,  DMODEL * DMODEL / 4);
    round_k<<<4096, 256>>>(fc1_w, wf1, FFDIM * DMODEL / 4);
    round_k<<<4096, 256>>>(fc2_w, wf2, FFDIM * DMODEL / 4);

    // 1) LN1
    ln_kernel<<<MROWS, 256>>>(x, ln1_w, ln1_b, hbuf);

    // 2) qkv = hbuf @ qkv_w^T + qkv_b
    gemm_tc<128,1,0,1><<<dim3(24, 32, 1), 256, 73728>>>(
        hbuf, wq, qkv_b, qkvp, nullptr, nullptr,
        DMODEL, DMODEL, DMODEL, 3 * DMODEL,
        0, 0, 0, 0, 0, 0, 1, 1.f);

    // 3) S[b,h] = (Q K^T) / 8
    gemm_tc<128,1,1,0><<<dim3(8, 8, 64), 256, 73728>>>(
        qkvp, qkvp + DMODEL, nullptr, S, nullptr, nullptr,
        DHEAD, 3 * DMODEL, 3 * DMODEL, NSEQ,
        SQK, DHEAD, SQK, DHEAD, (long long)NHEAD * NN, NN, NHEAD, 0.125f);

    // 4) talking-heads mix -> softmax -> mix
    attn_mix_softmax<<<BSZ * NSEQ, 512, 131072>>>(pl_w, pl_b, pw_w, pw_b, S);

    // 5) O[b,h] = P2 @ V
    gemm_tc<64,0,0,1><<<dim3(1, 8, 64), 256, 55296>>>(
        S, qkvp + 2 * DMODEL, nullptr, obuf, nullptr, nullptr,
        NSEQ, NSEQ, 3 * DMODEL, DMODEL,
        (long long)NHEAD * NN, NN, SQK, DHEAD,
        (long long)NSEQ * DMODEL, DHEAD, NHEAD, 1.f);

    // 6) x1 = x + gamma1 * (obuf @ out_w^T + out_b)
    gemm_tc<128,1,3,0><<<dim3(8, 32, 1), 256, 73728>>>(
        obuf, wo, out_b, out, x, gamma1,
        DMODEL, DMODEL, DMODEL, DMODEL,
        0, 0, 0, 0, 0, 0, 1, 1.f);

    // 7) LN2
    ln_kernel<<<MROWS, 256>>>(out, ln2_w, ln2_b, hbuf);

    // 8) ff = gelu(hbuf @ fc1_w^T + fc1_b)
    gemm_tc<128,1,2,1><<<dim3(32, 32, 1), 256, 73728>>>(
        hbuf, wf1, fc1_b, ff, nullptr, nullptr,
        DMODEL, DMODEL, DMODEL, FFDIM,
        0, 0, 0, 0, 0, 0, 1, 1.f);

    // 9) out = x1 + gamma2 * (ff @ fc2_w^T + fc2_b)
    gemm_tc<128,1,3,0><<<dim3(8, 32, 1), 256, 73728>>>(
        ff, wf2, fc2_b, out, out, gamma2,
        FFDIM, FFDIM, FFDIM, DMODEL,
        0, 0, 0, 0, 0, 0, 1, 1.f);
}